// round 1
// baseline (speedup 1.0000x reference)
#include <cuda_runtime.h>
#include <cstdint>
#include <cstddef>

#define TT   2048
#define BB   16
#define DIMK 1024
#define NN   64
#define MROWS (TT*BB)          // 32768 rows of the projection GEMM
#define CHUNK 16
#define NCH  (TT/CHUNK)        // 128 chunks

// ---------------- device scratch (no allocations allowed) ----------------
__device__ float scr_w[256 * 1024];          // packed [256][1024]: rows 0-63 Wk, 64-127 Wv, 128-191 Wq, 192-255 Wbeta
__device__ float scr_raw[(size_t)MROWS * 256]; // per row m=(t*B+b): [kn(64) | v(64) | q(64) | g(64)] after epilogue
__device__ float scr_c[MROWS];               // c = kn . q per (t,b)

// ---------------- f32x2 helpers ----------------
__device__ __forceinline__ unsigned long long pack2(float x, float y) {
    unsigned long long r;
    asm("mov.b64 %0, {%1, %2};" : "=l"(r) : "f"(x), "f"(y));
    return r;
}
__device__ __forceinline__ void unpack2(unsigned long long v, float &x, float &y) {
    asm("mov.b64 {%0, %1}, %2;" : "=f"(x), "=f"(y) : "l"(v));
}
__device__ __forceinline__ void ffma2(unsigned long long &c, unsigned long long a, unsigned long long b) {
    asm("fma.rn.f32x2 %0, %1, %2, %0;" : "+l"(c) : "l"(a), "l"(b));
}

// ---------------- cp.async helpers ----------------
__device__ __forceinline__ void cp_async16(void *smem_dst, const void *gsrc) {
    unsigned sa = (unsigned)__cvta_generic_to_shared(smem_dst);
    asm volatile("cp.async.ca.shared.global [%0], [%1], 16;" :: "r"(sa), "l"(gsrc));
}
__device__ __forceinline__ void cp_async4(void *smem_dst, const void *gsrc) {
    unsigned sa = (unsigned)__cvta_generic_to_shared(smem_dst);
    asm volatile("cp.async.ca.shared.global [%0], [%1], 4;" :: "r"(sa), "l"(gsrc));
}

// ======================================================================
// Kernel 0: pack the 4 weight matrices into one [256][1024] array
// ======================================================================
__global__ void copyw_kernel(const float *__restrict__ wk, const float *__restrict__ wv,
                             const float *__restrict__ wq, const float *__restrict__ wb) {
    int i = blockIdx.x * 256 + threadIdx.x;      // 0 .. 262143
    int sel = i >> 16;
    int off = i & 65535;
    const float *src = (sel == 0) ? wk : (sel == 1) ? wv : (sel == 2) ? wq : wb;
    scr_w[i] = src[off];
}

// ======================================================================
// Kernel 1: fp32 GEMM  C[32768,256] = X[32768,1024] @ Wpacked^T
// 128x128 tile, BK=16, 256 threads, 8x8 per thread, f32x2 inner product
// ======================================================================
__global__ __launch_bounds__(256, 2) void gemm_kernel(const float *__restrict__ X) {
    __shared__ __align__(16) float As[16 * 128];
    __shared__ __align__(16) float Bs[16 * 128];

    const int tid = threadIdx.x;
    const int m0 = blockIdx.x * 128;
    const int n0 = blockIdx.y * 128;
    const int tm = tid >> 4;      // 0..15
    const int tn = tid & 15;      // 0..15

    unsigned long long acc[4][8];
#pragma unroll
    for (int i = 0; i < 4; i++)
#pragma unroll
        for (int j = 0; j < 8; j++) acc[i][j] = 0ull;  // (0.f, 0.f)

    // global load assignment: 2 float4 units per thread per tile
    const int u0 = tid * 2;
    const int arow0 = u0 >> 2,      ac40 = u0 & 3;
    const int arow1 = (u0 + 1) >> 2, ac41 = (u0 + 1) & 3;

    const float *Xb = X + (size_t)m0 * DIMK;
    const float *Wb = scr_w + (size_t)n0 * DIMK;

    for (int kt = 0; kt < DIMK; kt += 16) {
        float4 a0 = *(const float4 *)(Xb + (size_t)arow0 * DIMK + kt + ac40 * 4);
        float4 a1 = *(const float4 *)(Xb + (size_t)arow1 * DIMK + kt + ac41 * 4);
        float4 b0 = *(const float4 *)(Wb + (size_t)arow0 * DIMK + kt + ac40 * 4);
        float4 b1 = *(const float4 *)(Wb + (size_t)arow1 * DIMK + kt + ac41 * 4);

        __syncthreads();  // previous iteration's reads must finish before overwrite
        {
            int k0 = ac40 * 4, k1 = ac41 * 4;
            As[(k0 + 0) * 128 + arow0] = a0.x; As[(k0 + 1) * 128 + arow0] = a0.y;
            As[(k0 + 2) * 128 + arow0] = a0.z; As[(k0 + 3) * 128 + arow0] = a0.w;
            As[(k1 + 0) * 128 + arow1] = a1.x; As[(k1 + 1) * 128 + arow1] = a1.y;
            As[(k1 + 2) * 128 + arow1] = a1.z; As[(k1 + 3) * 128 + arow1] = a1.w;
            Bs[(k0 + 0) * 128 + arow0] = b0.x; Bs[(k0 + 1) * 128 + arow0] = b0.y;
            Bs[(k0 + 2) * 128 + arow0] = b0.z; Bs[(k0 + 3) * 128 + arow0] = b0.w;
            Bs[(k1 + 0) * 128 + arow1] = b1.x; Bs[(k1 + 1) * 128 + arow1] = b1.y;
            Bs[(k1 + 2) * 128 + arow1] = b1.z; Bs[(k1 + 3) * 128 + arow1] = b1.w;
        }
        __syncthreads();

#pragma unroll
        for (int k = 0; k < 16; k++) {
            const ulonglong2 *pa = (const ulonglong2 *)&As[k * 128 + tm * 8];
            ulonglong2 av0 = pa[0];
            ulonglong2 av1 = pa[1];
            float4 bv0 = *(const float4 *)&Bs[k * 128 + tn * 8];
            float4 bv1 = *(const float4 *)&Bs[k * 128 + tn * 8 + 4];
            unsigned long long ap[4] = {av0.x, av0.y, av1.x, av1.y};
            unsigned long long bb[8];
            bb[0] = pack2(bv0.x, bv0.x); bb[1] = pack2(bv0.y, bv0.y);
            bb[2] = pack2(bv0.z, bv0.z); bb[3] = pack2(bv0.w, bv0.w);
            bb[4] = pack2(bv1.x, bv1.x); bb[5] = pack2(bv1.y, bv1.y);
            bb[6] = pack2(bv1.z, bv1.z); bb[7] = pack2(bv1.w, bv1.w);
#pragma unroll
            for (int mp = 0; mp < 4; mp++)
#pragma unroll
                for (int n = 0; n < 8; n++)
                    ffma2(acc[mp][n], ap[mp], bb[n]);
        }
    }

    // writeback
#pragma unroll
    for (int mp = 0; mp < 4; mp++) {
        float lo[8], hi[8];
#pragma unroll
        for (int n = 0; n < 8; n++) unpack2(acc[mp][n], lo[n], hi[n]);
        int mA = m0 + tm * 8 + mp * 2;
        float *outp = scr_raw + (size_t)mA * 256 + n0 + tn * 8;
        *(float4 *)(outp)           = make_float4(lo[0], lo[1], lo[2], lo[3]);
        *(float4 *)(outp + 4)       = make_float4(lo[4], lo[5], lo[6], lo[7]);
        *(float4 *)(outp + 256)     = make_float4(hi[0], hi[1], hi[2], hi[3]);
        *(float4 *)(outp + 256 + 4) = make_float4(hi[4], hi[5], hi[6], hi[7]);
    }
}

// ======================================================================
// Kernel 2: epilogue — in-place per-row: kn = k/(|k|+eps), g = sigmoid(beta+b),
//           c = kn . q   (one warp per (t,b) row)
// ======================================================================
__global__ void epilogue_kernel(const float *__restrict__ b_beta) {
    int warp = (blockIdx.x * blockDim.x + threadIdx.x) >> 5;
    int lane = threadIdx.x & 31;
    if (warp >= MROWS) return;
    float *row = scr_raw + (size_t)warp * 256;
    int i0 = lane * 2;

    float2 kv = *(float2 *)(row + i0);
    float2 qv = *(float2 *)(row + 128 + i0);
    float2 bt = *(float2 *)(row + 192 + i0);

    float nk = kv.x * kv.x + kv.y * kv.y;
#pragma unroll
    for (int off = 16; off; off >>= 1) nk += __shfl_xor_sync(0xffffffffu, nk, off);
    float inv = 1.0f / (sqrtf(nk) + 1e-6f);
    float knx = kv.x * inv, kny = kv.y * inv;

    float cp = knx * qv.x + kny * qv.y;
#pragma unroll
    for (int off = 16; off; off >>= 1) cp += __shfl_xor_sync(0xffffffffu, cp, off);

    float gx = 1.0f / (1.0f + __expf(-(bt.x + b_beta[i0])));
    float gy = 1.0f / (1.0f + __expf(-(bt.y + b_beta[i0 + 1])));

    *(float2 *)(row + i0)       = make_float2(knx, kny);
    *(float2 *)(row + 192 + i0) = make_float2(gx, gy);
    if (lane == 0) scr_c[warp] = cp;
}

// ======================================================================
// Kernel 3: the sequential scan. grid (B=16, 8 row-groups), 64 threads.
// Each thread owns 8 state floats of one row. cp.async double-buffered
// input staging, CHUNK=16 steps per stage.
// ======================================================================
__device__ __forceinline__ void issue_chunk(float *kn_s, float *q_s, float *v_s,
                                            float *g_s, float *c_s,
                                            int t0, int b, int r0, int tid) {
    // kn and q: 16 steps * 64 floats = 256 float4 each
#pragma unroll
    for (int i = 0; i < 4; i++) {
        int u = tid + i * 64;
        int st = u >> 4, f4 = u & 15;
        size_t m = (size_t)(t0 + st) * BB + b;
        cp_async16(kn_s + st * 64 + f4 * 4, scr_raw + m * 256 + f4 * 4);
        cp_async16(q_s  + st * 64 + f4 * 4, scr_raw + m * 256 + 128 + f4 * 4);
    }
    if (tid < 32) {   // v: 16 steps * 8 floats (this block's rows)
        int st = tid >> 1, part = tid & 1;
        size_t m = (size_t)(t0 + st) * BB + b;
        cp_async16(v_s + st * 8 + part * 4, scr_raw + m * 256 + 64 + r0 + part * 4);
    } else {          // g: same slice
        int u = tid - 32;
        int st = u >> 1, part = u & 1;
        size_t m = (size_t)(t0 + st) * BB + b;
        cp_async16(g_s + st * 8 + part * 4, scr_raw + m * 256 + 192 + r0 + part * 4);
    }
    if (tid < CHUNK) {
        size_t m = (size_t)(t0 + tid) * BB + b;
        cp_async4(c_s + tid, scr_c + m);
    }
}

__global__ __launch_bounds__(64) void scan_kernel(const float *__restrict__ S0,
                                                  float *__restrict__ out,
                                                  int write_sfinal) {
    __shared__ __align__(16) float sh_kn[2][CHUNK][64];
    __shared__ __align__(16) float sh_q[2][CHUNK][64];
    __shared__ __align__(16) float sh_v[2][CHUNK][8];
    __shared__ __align__(16) float sh_g[2][CHUNK][8];
    __shared__ float sh_c[2][CHUNK];
    __shared__ float sh_out[CHUNK][8];

    const int b  = blockIdx.x;       // batch
    const int r0 = blockIdx.y * 8;   // first row of this group
    const int tid = threadIdx.x;
    const int rl = tid >> 3;         // row-local 0..7
    const int cg = tid & 7;          // column group
    const int j0 = cg * 8;
    const int row = r0 + rl;

    float s[8];
    const float *s0p = S0 + ((size_t)b * 64 + row) * 64 + j0;
#pragma unroll
    for (int j = 0; j < 8; j++) s[j] = s0p[j];

    issue_chunk(&sh_kn[0][0][0], &sh_q[0][0][0], &sh_v[0][0][0], &sh_g[0][0][0],
                &sh_c[0][0], 0, b, r0, tid);
    asm volatile("cp.async.commit_group;");

    for (int ch = 0; ch < NCH; ch++) {
        const int pb = ch & 1;
        if (ch + 1 < NCH) {
            issue_chunk(&sh_kn[pb ^ 1][0][0], &sh_q[pb ^ 1][0][0], &sh_v[pb ^ 1][0][0],
                        &sh_g[pb ^ 1][0][0], &sh_c[pb ^ 1][0],
                        (ch + 1) * CHUNK, b, r0, tid);
            asm volatile("cp.async.commit_group;");
            asm volatile("cp.async.wait_group 1;");
        } else {
            asm volatile("cp.async.wait_group 0;");
        }
        __syncthreads();

#pragma unroll 1
        for (int st = 0; st < CHUNK; st++) {
            float4 k0 = *(const float4 *)&sh_kn[pb][st][j0];
            float4 k1 = *(const float4 *)&sh_kn[pb][st][j0 + 4];
            float4 q0 = *(const float4 *)&sh_q[pb][st][j0];
            float4 q1 = *(const float4 *)&sh_q[pb][st][j0 + 4];

            // two mat-vec partial dots on OLD S, interleaved (2 accumulators each)
            float rka = s[0] * k0.x,            rkb = s[1] * k0.y;
            float rqa = s[0] * q0.x,            rqb = s[1] * q0.y;
            rka = fmaf(s[2], k0.z, rka);        rkb = fmaf(s[3], k0.w, rkb);
            rqa = fmaf(s[2], q0.z, rqa);        rqb = fmaf(s[3], q0.w, rqb);
            rka = fmaf(s[4], k1.x, rka);        rkb = fmaf(s[5], k1.y, rkb);
            rqa = fmaf(s[4], q1.x, rqa);        rqb = fmaf(s[5], q1.y, rqb);
            rka = fmaf(s[6], k1.z, rka);        rkb = fmaf(s[7], k1.w, rkb);
            rqa = fmaf(s[6], q1.z, rqa);        rqb = fmaf(s[7], q1.w, rqb);
            float rk = rka + rkb;
            float rq = rqa + rqb;

            // reduce over the 8 threads of this row (lanes differ in bits 0..2)
            rk += __shfl_xor_sync(0xffffffffu, rk, 1);
            rq += __shfl_xor_sync(0xffffffffu, rq, 1);
            rk += __shfl_xor_sync(0xffffffffu, rk, 2);
            rq += __shfl_xor_sync(0xffffffffu, rq, 2);
            rk += __shfl_xor_sync(0xffffffffu, rk, 4);
            rq += __shfl_xor_sync(0xffffffffu, rq, 4);

            float v = sh_v[pb][st][rl];
            float g = sh_g[pb][st][rl];
            float c = sh_c[pb][st];
            float delta = v - rk;
            // Sq = S_new . q = g*(S.q) + delta*(kn.q)   (exact algebra)
            float Sq = fmaf(g, rq, delta * c);
            if (cg == 0) {
                float sg = 1.0f / (1.0f + __expf(-Sq));
                sh_out[st][rl] = Sq * Sq * sg;   // Sq * silu(Sq)
            }
            // state update
            s[0] = fmaf(g, s[0], delta * k0.x);
            s[1] = fmaf(g, s[1], delta * k0.y);
            s[2] = fmaf(g, s[2], delta * k0.z);
            s[3] = fmaf(g, s[3], delta * k0.w);
            s[4] = fmaf(g, s[4], delta * k1.x);
            s[5] = fmaf(g, s[5], delta * k1.y);
            s[6] = fmaf(g, s[6], delta * k1.z);
            s[7] = fmaf(g, s[7], delta * k1.w);
        }
        __syncthreads();   // sh_out complete; buffer pb free for re-issue

        // flush outputs for this chunk: 128 floats, 2 per thread
        const int t0 = ch * CHUNK;
#pragma unroll
        for (int u = 0; u < 2; u++) {
            int idx = tid + u * 64;
            int st = idx >> 3, r = idx & 7;
            out[(size_t)(t0 + st) * (BB * NN) + b * NN + r0 + r] = sh_out[st][r];
        }
    }

    if (write_sfinal) {
        float *sf = out + (size_t)TT * BB * NN + ((size_t)b * 64 + row) * 64 + j0;
        *(float4 *)sf       = make_float4(s[0], s[1], s[2], s[3]);
        *(float4 *)(sf + 4) = make_float4(s[4], s[5], s[6], s[7]);
    }
}

// ======================================================================
extern "C" void kernel_launch(void *const *d_in, const int *in_sizes, int n_in,
                              void *d_out, int out_size) {
    const float *x  = (const float *)d_in[0];
    const float *S0 = (const float *)d_in[1];
    const float *Wk = (const float *)d_in[2];
    const float *Wv = (const float *)d_in[3];
    const float *Wq = (const float *)d_in[4];
    const float *Wb = (const float *)d_in[5];
    const float *bb = (const float *)d_in[6];
    float *out = (float *)d_out;

    copyw_kernel<<<1024, 256>>>(Wk, Wv, Wq, Wb);
    gemm_kernel<<<dim3(MROWS / 128, 2), 256>>>(x);
    epilogue_kernel<<<4096, 256>>>(bb);

    int ws = (out_size >= TT * BB * NN + BB * NN * NN) ? 1 : 0;
    scan_kernel<<<dim3(BB, 8), 64>>>(S0, out, ws);
}

// round 3
// speedup vs baseline: 1.7006x; 1.7006x over previous
#include <cuda_runtime.h>
#include <cuda_bf16.h>
#include <cstdint>
#include <cstddef>

#define TT   2048
#define BB   16
#define DIMK 1024
#define NN   64
#define NTOT 256
#define MROWS (TT*BB)
#define CHUNK 16
#define CH17  (CHUNK+1)
#define NCH   (TT/CHUNK)

// Does this compilation pass support tcgen05 (arch-specific sm_100a/sm_103a)?
#if defined(__CUDA_ARCH__) && (__CUDA_ARCH__ >= 1000) && \
    (defined(__CUDA_ARCH_FEAT_SM103_ALL) || defined(__CUDA_ARCH_FEAT_SM100_ALL))
#define HAS_TC 1
#else
#define HAS_TC 0
#endif

// ---------------- device scratch ----------------
__device__ __align__(128) __nv_bfloat16 g_xhi[(size_t)MROWS * DIMK];
__device__ __align__(128) __nv_bfloat16 g_xlo[(size_t)MROWS * DIMK];
__device__ __align__(128) __nv_bfloat16 g_whi[NTOT * DIMK];
__device__ __align__(128) __nv_bfloat16 g_wlo[NTOT * DIMK];
__device__ __align__(128) float scr_w[NTOT * DIMK];   // packed fp32 weights (fallback path)
// per row m=(t*B+b): [kn(64)|v(64)|q(64)|g(64)]; +1 timestep of zero pad
__device__ __align__(128) float scr_raw[(size_t)(MROWS + BB) * NTOT];
__device__ float scr_c[MROWS + BB];   // kn_t . q_t
__device__ float scr_d[MROWS + BB];   // kn_t . kn_{t+1}
__device__ float scr_e[MROWS + BB];   // kn_t . q_{t+1}

// ---------------- helpers ----------------
#define SWZ(off) ((off) ^ (((off) >> 3) & 0x70))

__device__ __forceinline__ void cp_async16(void *smem_dst, const void *gsrc) {
    unsigned sa = (unsigned)__cvta_generic_to_shared(smem_dst);
    asm volatile("cp.async.ca.shared.global [%0], [%1], 16;" :: "r"(sa), "l"(gsrc));
}
__device__ __forceinline__ void cp_async4(void *smem_dst, const void *gsrc) {
    unsigned sa = (unsigned)__cvta_generic_to_shared(smem_dst);
    asm volatile("cp.async.ca.shared.global [%0], [%1], 4;" :: "r"(sa), "l"(gsrc));
}

// f32x2 helpers (fallback GEMM)
__device__ __forceinline__ unsigned long long pack2(float x, float y) {
    unsigned long long r;
    asm("mov.b64 %0, {%1, %2};" : "=l"(r) : "f"(x), "f"(y));
    return r;
}
__device__ __forceinline__ void unpack2(unsigned long long v, float &x, float &y) {
    asm("mov.b64 {%0, %1}, %2;" : "=f"(x), "=f"(y) : "l"(v));
}
__device__ __forceinline__ void ffma2(unsigned long long &c, unsigned long long a, unsigned long long b) {
    asm("fma.rn.f32x2 %0, %1, %2, %0;" : "+l"(c) : "l"(a), "l"(b));
}

// split fp32 -> (hi, lo) bf16
__device__ __forceinline__ void split4(float4 v, uint2 &uh, uint2 &ul) {
    __nv_bfloat16 h0 = __float2bfloat16(v.x), h1 = __float2bfloat16(v.y);
    __nv_bfloat16 h2 = __float2bfloat16(v.z), h3 = __float2bfloat16(v.w);
    __nv_bfloat16 l0 = __float2bfloat16(v.x - __bfloat162float(h0));
    __nv_bfloat16 l1 = __float2bfloat16(v.y - __bfloat162float(h1));
    __nv_bfloat16 l2 = __float2bfloat16(v.z - __bfloat162float(h2));
    __nv_bfloat16 l3 = __float2bfloat16(v.w - __bfloat16_as_ushort(h3) * 0.0f - __bfloat162float(h3));
    uh.x = ((uint32_t)__bfloat16_as_ushort(h1) << 16) | __bfloat16_as_ushort(h0);
    uh.y = ((uint32_t)__bfloat16_as_ushort(h3) << 16) | __bfloat16_as_ushort(h2);
    ul.x = ((uint32_t)__bfloat16_as_ushort(l1) << 16) | __bfloat16_as_ushort(l0);
    ul.y = ((uint32_t)__bfloat16_as_ushort(l3) << 16) | __bfloat16_as_ushort(l2);
}

#if HAS_TC
__device__ __forceinline__ uint64_t make_desc(uint32_t a) {
    return ((uint64_t)2 << 61) | ((uint64_t)1 << 46) | ((uint64_t)64 << 32) |
           ((uint64_t)1 << 16) | ((a >> 4) & 0x3FFF);
}
__device__ __forceinline__ void mbar_init(uint32_t addr, uint32_t cnt) {
    asm volatile("mbarrier.init.shared.b64 [%0], %1;" :: "r"(addr), "r"(cnt) : "memory");
}
__device__ __forceinline__ void mbar_wait(uint32_t addr, uint32_t parity) {
    uint32_t done;
    asm volatile(
        "{\n\t.reg .pred p;\n\t"
        "mbarrier.try_wait.parity.acquire.cta.shared::cta.b64 p, [%1], %2;\n\t"
        "selp.b32 %0, 1, 0, p;\n\t}"
        : "=r"(done) : "r"(addr), "r"(parity) : "memory");
    if (!done) {
        asm volatile(
            "{\n\t.reg .pred P1;\n\t"
            "WL_%=:\n\t"
            "mbarrier.try_wait.parity.acquire.cta.shared::cta.b64 P1, [%0], %1, 0x989680;\n\t"
            "@P1 bra.uni WD_%=;\n\t"
            "bra.uni WL_%=;\n\t"
            "WD_%=:\n\t}"
            :: "r"(addr), "r"(parity) : "memory");
    }
}
__device__ __forceinline__ void mma_f16_ss(uint32_t d, uint64_t a, uint64_t b,
                                           uint32_t idesc, uint32_t en) {
    asm volatile(
        "{\n\t.reg .pred p;\n\t"
        "setp.ne.u32 p, %5, 0;\n\t"
        "tcgen05.mma.cta_group::1.kind::f16 [%0], %1, %2, %3, {%4, %4, %4, %4}, p;\n\t}"
        :: "r"(d), "l"(a), "l"(b), "r"(idesc), "r"(0u), "r"(en) : "memory");
}
#endif

// ======================================================================
// Weight prep kernels.  copyw always runs (fallback needs it, cheap).
// convw/convx only do work in the tcgen05 pass.
// ======================================================================
__global__ void copyw_kernel(const float *__restrict__ wk, const float *__restrict__ wv,
                             const float *__restrict__ wq, const float *__restrict__ wb) {
#if !HAS_TC
    int i = blockIdx.x * 256 + threadIdx.x;
    int sel = i >> 16, off = i & 65535;
    const float *src = (sel == 0) ? wk : (sel == 1) ? wv : (sel == 2) ? wq : wb;
    scr_w[i] = src[off];
#endif
}

__global__ void convw_kernel(const float *__restrict__ wk, const float *__restrict__ wv,
                             const float *__restrict__ wq, const float *__restrict__ wb) {
#if HAS_TC
    int g = blockIdx.x * 256 + threadIdx.x;
    int i4 = g * 4;
    int n = i4 >> 10, k = i4 & 1023;
    int sel = n >> 6, r = n & 63;
    const float *src = (sel == 0) ? wk : (sel == 1) ? wv : (sel == 2) ? wq : wb;
    float4 v = *(const float4 *)(src + (size_t)r * DIMK + k);
    uint2 uh, ul;
    split4(v, uh, ul);
    *(uint2 *)(g_whi + i4) = uh;
    *(uint2 *)(g_wlo + i4) = ul;
#endif
}

__global__ void convx_kernel(const float *__restrict__ x) {
#if HAS_TC
    size_t i4 = ((size_t)blockIdx.x * 256 + threadIdx.x) * 4;
    float4 v = *(const float4 *)(x + i4);
    uint2 uh, ul;
    split4(v, uh, ul);
    *(uint2 *)(g_xhi + i4) = uh;
    *(uint2 *)(g_xlo + i4) = ul;
#endif
}

// ======================================================================
// Fallback fp32 GEMM (body only in non-tcgen05 passes)
// C[32768,256] = X @ Wpacked^T, 128x128 tile, BK=16, f32x2 inner product
// ======================================================================
__global__ __launch_bounds__(256, 2) void fb_gemm_kernel(const float *__restrict__ X) {
#if !HAS_TC
    __shared__ __align__(16) float As[16 * 128];
    __shared__ __align__(16) float Bs[16 * 128];

    const int tid = threadIdx.x;
    const int m0 = blockIdx.x * 128;
    const int n0 = blockIdx.y * 128;
    const int tm = tid >> 4;
    const int tn = tid & 15;

    unsigned long long acc[4][8];
#pragma unroll
    for (int i = 0; i < 4; i++)
#pragma unroll
        for (int j = 0; j < 8; j++) acc[i][j] = 0ull;

    const int u0 = tid * 2;
    const int arow0 = u0 >> 2,       ac40 = u0 & 3;
    const int arow1 = (u0 + 1) >> 2, ac41 = (u0 + 1) & 3;

    const float *Xb = X + (size_t)m0 * DIMK;
    const float *Wb = scr_w + (size_t)n0 * DIMK;

    for (int kt = 0; kt < DIMK; kt += 16) {
        float4 a0 = *(const float4 *)(Xb + (size_t)arow0 * DIMK + kt + ac40 * 4);
        float4 a1 = *(const float4 *)(Xb + (size_t)arow1 * DIMK + kt + ac41 * 4);
        float4 b0 = *(const float4 *)(Wb + (size_t)arow0 * DIMK + kt + ac40 * 4);
        float4 b1 = *(const float4 *)(Wb + (size_t)arow1 * DIMK + kt + ac41 * 4);

        __syncthreads();
        {
            int k0 = ac40 * 4, k1 = ac41 * 4;
            As[(k0 + 0) * 128 + arow0] = a0.x; As[(k0 + 1) * 128 + arow0] = a0.y;
            As[(k0 + 2) * 128 + arow0] = a0.z; As[(k0 + 3) * 128 + arow0] = a0.w;
            As[(k1 + 0) * 128 + arow1] = a1.x; As[(k1 + 1) * 128 + arow1] = a1.y;
            As[(k1 + 2) * 128 + arow1] = a1.z; As[(k1 + 3) * 128 + arow1] = a1.w;
            Bs[(k0 + 0) * 128 + arow0] = b0.x; Bs[(k0 + 1) * 128 + arow0] = b0.y;
            Bs[(k0 + 2) * 128 + arow0] = b0.z; Bs[(k0 + 3) * 128 + arow0] = b0.w;
            Bs[(k1 + 0) * 128 + arow1] = b1.x; Bs[(k1 + 1) * 128 + arow1] = b1.y;
            Bs[(k1 + 2) * 128 + arow1] = b1.z; Bs[(k1 + 3) * 128 + arow1] = b1.w;
        }
        __syncthreads();

#pragma unroll
        for (int k = 0; k < 16; k++) {
            const ulonglong2 *pa = (const ulonglong2 *)&As[k * 128 + tm * 8];
            ulonglong2 av0 = pa[0];
            ulonglong2 av1 = pa[1];
            float4 bv0 = *(const float4 *)&Bs[k * 128 + tn * 8];
            float4 bv1 = *(const float4 *)&Bs[k * 128 + tn * 8 + 4];
            unsigned long long ap[4] = {av0.x, av0.y, av1.x, av1.y};
            unsigned long long bbx[8];
            bbx[0] = pack2(bv0.x, bv0.x); bbx[1] = pack2(bv0.y, bv0.y);
            bbx[2] = pack2(bv0.z, bv0.z); bbx[3] = pack2(bv0.w, bv0.w);
            bbx[4] = pack2(bv1.x, bv1.x); bbx[5] = pack2(bv1.y, bv1.y);
            bbx[6] = pack2(bv1.z, bv1.z); bbx[7] = pack2(bv1.w, bv1.w);
#pragma unroll
            for (int mp = 0; mp < 4; mp++)
#pragma unroll
                for (int n = 0; n < 8; n++)
                    ffma2(acc[mp][n], ap[mp], bbx[n]);
        }
    }

#pragma unroll
    for (int mp = 0; mp < 4; mp++) {
        float lo[8], hi[8];
#pragma unroll
        for (int n = 0; n < 8; n++) unpack2(acc[mp][n], lo[n], hi[n]);
        int mA = m0 + tm * 8 + mp * 2;
        float *outp = scr_raw + (size_t)mA * NTOT + n0 + tn * 8;
        *(float4 *)(outp)           = make_float4(lo[0], lo[1], lo[2], lo[3]);
        *(float4 *)(outp + 4)       = make_float4(lo[4], lo[5], lo[6], lo[7]);
        *(float4 *)(outp + NTOT)     = make_float4(hi[0], hi[1], hi[2], hi[3]);
        *(float4 *)(outp + NTOT + 4) = make_float4(hi[4], hi[5], hi[6], hi[7]);
    }
#endif
}

// ======================================================================
// tcgen05 GEMM (body only in arch-specific passes)
// ======================================================================
#define GK 64
#define NKC (DIMK / GK)
#define A_BYTES  (128 * 128)
#define B_BYTES  (256 * 128)
#define ST_BYTES (2 * A_BYTES + 2 * B_BYTES)          // 96 KB
#define SMEM_GEMM_TOTAL (1024 + 2 * ST_BYTES)
#define G_IDESC ((1u << 4) | (1u << 7) | (1u << 10) | ((NTOT / 8) << 17) | ((128 / 16) << 24))

extern __shared__ __align__(1024) char gsm[];

#if HAS_TC
__device__ __forceinline__ void g_load_chunk(char *stp, int m0, int kc, int tid) {
    const char *xh = (const char *)(g_xhi + (size_t)m0 * DIMK + kc * GK);
    const char *xl = (const char *)(g_xlo + (size_t)m0 * DIMK + kc * GK);
#pragma unroll
    for (int i = 0; i < 8; i++) {
        int idx = tid + i * 128;
        int row = idx >> 3, gr = idx & 7;
        uint32_t sw = SWZ(row * 128 + gr * 16);
        size_t gof = (size_t)row * (DIMK * 2) + gr * 16;
        cp_async16(stp + sw, xh + gof);
        cp_async16(stp + A_BYTES + sw, xl + gof);
    }
    const char *wh = (const char *)(g_whi + kc * GK);
    const char *wl = (const char *)(g_wlo + kc * GK);
#pragma unroll
    for (int i = 0; i < 16; i++) {
        int idx = tid + i * 128;
        int row = idx >> 3, gr = idx & 7;
        uint32_t sw = SWZ(row * 128 + gr * 16);
        size_t gof = (size_t)row * (DIMK * 2) + gr * 16;
        cp_async16(stp + 2 * A_BYTES + sw, wh + gof);
        cp_async16(stp + 2 * A_BYTES + B_BYTES + sw, wl + gof);
    }
}
#endif

__global__ __launch_bounds__(128, 1)
void mma_gemm_kernel() {
#if HAS_TC
    const int tid = threadIdx.x, wid = tid >> 5, lid = tid & 31;
    const int m0 = blockIdx.x * 128;
    uint32_t sbase = (uint32_t)__cvta_generic_to_shared(gsm);

    if (wid == 0) {
        asm volatile("tcgen05.alloc.cta_group::1.sync.aligned.shared::cta.b32 [%0], %1;"
                     :: "r"(sbase), "r"(256u) : "memory");
        asm volatile("tcgen05.relinquish_alloc_permit.cta_group::1.sync.aligned;");
    }
    if (tid == 0) { mbar_init(sbase + 16, 1); mbar_init(sbase + 24, 1); }
    __syncthreads();
    uint32_t tmem;
    asm volatile("ld.shared.b32 %0, [%1];" : "=r"(tmem) : "r"(sbase));

    g_load_chunk(gsm + 1024, m0, 0, tid);
    asm volatile("cp.async.commit_group;");
    g_load_chunk(gsm + 1024 + ST_BYTES, m0, 1, tid);
    asm volatile("cp.async.commit_group;");

    int ph0 = 0, ph1 = 0;
    for (int c = 0; c < NKC; c++) {
        int s = c & 1;
        char *stp = gsm + 1024 + s * ST_BYTES;
        uint32_t sa = sbase + 1024 + s * ST_BYTES;
        if (c < NKC - 1) asm volatile("cp.async.wait_group 1;" ::: "memory");
        else             asm volatile("cp.async.wait_group 0;" ::: "memory");
        __syncthreads();

        if (tid == 0) {
            asm volatile("fence.proxy.async.shared::cta;" ::: "memory");
            uint64_t ahi = make_desc(sa);
            uint64_t alo = make_desc(sa + A_BYTES);
            uint64_t bhi = make_desc(sa + 2 * A_BYTES);
            uint64_t blo = make_desc(sa + 2 * A_BYTES + B_BYTES);
#pragma unroll
            for (int k = 0; k < 4; k++)
                mma_f16_ss(tmem, ahi + k * 2, bhi + k * 2, G_IDESC, !(c == 0 && k == 0));
#pragma unroll
            for (int k = 0; k < 4; k++)
                mma_f16_ss(tmem, ahi + k * 2, blo + k * 2, G_IDESC, 1u);
#pragma unroll
            for (int k = 0; k < 4; k++)
                mma_f16_ss(tmem, alo + k * 2, bhi + k * 2, G_IDESC, 1u);
            asm volatile(
                "tcgen05.commit.cta_group::1.mbarrier::arrive::one.shared::cluster.b64 [%0];"
                :: "r"(sbase + 16 + s * 8) : "memory");
        }
        if (c + 2 < NKC) {
            if (s == 0) { mbar_wait(sbase + 16, ph0 & 1); ph0++; }
            else        { mbar_wait(sbase + 24, ph1 & 1); ph1++; }
            g_load_chunk(stp, m0, c + 2, tid);
            asm volatile("cp.async.commit_group;");
        }
    }
    mbar_wait(sbase + 16, ph0 & 1);
    mbar_wait(sbase + 24, ph1 & 1);
    asm volatile("tcgen05.fence::after_thread_sync;" ::: "memory");

    float *orow = scr_raw + (size_t)(m0 + wid * 32 + lid) * NTOT;
#pragma unroll 1
    for (int cb = 0; cb < 8; cb++) {
        uint32_t r[32];
        asm volatile(
            "tcgen05.ld.sync.aligned.32x32b.x32.b32 "
            "{%0, %1, %2, %3, %4, %5, %6, %7, "
            " %8, %9, %10, %11, %12, %13, %14, %15, "
            " %16, %17, %18, %19, %20, %21, %22, %23, "
            " %24, %25, %26, %27, %28, %29, %30, %31}, [%32];"
            : "=r"(r[0]), "=r"(r[1]), "=r"(r[2]), "=r"(r[3]), "=r"(r[4]), "=r"(r[5]),
              "=r"(r[6]), "=r"(r[7]), "=r"(r[8]), "=r"(r[9]), "=r"(r[10]), "=r"(r[11]),
              "=r"(r[12]), "=r"(r[13]), "=r"(r[14]), "=r"(r[15]), "=r"(r[16]), "=r"(r[17]),
              "=r"(r[18]), "=r"(r[19]), "=r"(r[20]), "=r"(r[21]), "=r"(r[22]), "=r"(r[23]),
              "=r"(r[24]), "=r"(r[25]), "=r"(r[26]), "=r"(r[27]), "=r"(r[28]), "=r"(r[29]),
              "=r"(r[30]), "=r"(r[31])
            : "r"(tmem + cb * 32));
        asm volatile("tcgen05.wait::ld.sync.aligned;" ::: "memory");
        float4 *o4 = (float4 *)(orow + cb * 32);
#pragma unroll
        for (int i = 0; i < 8; i++)
            o4[i] = make_float4(__uint_as_float(r[i * 4]), __uint_as_float(r[i * 4 + 1]),
                                __uint_as_float(r[i * 4 + 2]), __uint_as_float(r[i * 4 + 3]));
    }
    __syncthreads();
    if (wid == 0)
        asm volatile("tcgen05.dealloc.cta_group::1.sync.aligned.b32 %0, %1;"
                     :: "r"(tmem), "r"(256u));
#endif
}

// ======================================================================
// Epilogue: kn = k/(|k|+eps), g = sigmoid(beta+b), c = kn.q   (1 warp/row)
// ======================================================================
__global__ void epilogue_kernel(const float *__restrict__ b_beta) {
    int warp = (blockIdx.x * blockDim.x + threadIdx.x) >> 5;
    int lane = threadIdx.x & 31;
    if (warp >= MROWS) return;
    float *row = scr_raw + (size_t)warp * NTOT;
    int i0 = lane * 2;

    float2 kv = *(float2 *)(row + i0);
    float2 qv = *(float2 *)(row + 128 + i0);
    float2 bt = *(float2 *)(row + 192 + i0);

    float nk = kv.x * kv.x + kv.y * kv.y;
#pragma unroll
    for (int off = 16; off; off >>= 1) nk += __shfl_xor_sync(0xffffffffu, nk, off);
    float inv = 1.0f / (sqrtf(nk) + 1e-6f);
    float knx = kv.x * inv, kny = kv.y * inv;

    float cp = knx * qv.x + kny * qv.y;
#pragma unroll
    for (int off = 16; off; off >>= 1) cp += __shfl_xor_sync(0xffffffffu, cp, off);

    float gx = 1.0f / (1.0f + __expf(-(bt.x + b_beta[i0])));
    float gy = 1.0f / (1.0f + __expf(-(bt.y + b_beta[i0 + 1])));

    *(float2 *)(row + i0)       = make_float2(knx, kny);
    *(float2 *)(row + 192 + i0) = make_float2(gx, gy);
    if (lane == 0) scr_c[warp] = cp;
}

// ======================================================================
// Pair kernel: d_m = kn_m . kn_{m+B},  e_m = kn_m . q_{m+B}
// ======================================================================
__global__ void pair_kernel() {
    int warp = (blockIdx.x * blockDim.x + threadIdx.x) >> 5;
    int lane = threadIdx.x & 31;
    if (warp >= MROWS) return;
    const float *r0 = scr_raw + (size_t)warp * NTOT;
    const float *r1 = scr_raw + (size_t)(warp + BB) * NTOT;
    int i0 = lane * 2;

    float2 k0 = *(const float2 *)(r0 + i0);
    float2 k1 = *(const float2 *)(r1 + i0);
    float2 q1 = *(const float2 *)(r1 + 128 + i0);

    float d = k0.x * k1.x + k0.y * k1.y;
    float e = k0.x * q1.x + k0.y * q1.y;
#pragma unroll
    for (int off = 16; off; off >>= 1) {
        d += __shfl_xor_sync(0xffffffffu, d, off);
        e += __shfl_xor_sync(0xffffffffu, e, off);
    }
    if (lane == 0) { scr_d[warp] = d; scr_e[warp] = e; }
}

// ======================================================================
// Scan with one-step lookahead. grid (B=16, 8 groups), 64 threads.
// ======================================================================
__device__ __forceinline__ void scan_issue(float *kn_s, float *q_s, float *v_s, float *g_s,
                                           float *c_s, float *d_s, float *e_s,
                                           int t0, int b, int r0, int tid) {
#pragma unroll
    for (int i = 0; i < 5; i++) {
        int u = tid + i * 64;
        if (u < CH17 * 16) {
            int st = u >> 4, f4 = u & 15;
            size_t m = (size_t)(t0 + st) * BB + b;
            cp_async16(kn_s + st * 64 + f4 * 4, scr_raw + m * NTOT + f4 * 4);
            cp_async16(q_s  + st * 64 + f4 * 4, scr_raw + m * NTOT + 128 + f4 * 4);
        }
    }
    {
        int st = (tid & 31) >> 1, part = tid & 1;
        size_t m = (size_t)(t0 + st) * BB + b;
        if (tid < 32) cp_async16(v_s + st * 8 + part * 4, scr_raw + m * NTOT + 64 + r0 + part * 4);
        else          cp_async16(g_s + st * 8 + part * 4, scr_raw + m * NTOT + 192 + r0 + part * 4);
    }
    if (tid < 48) {
        int st = tid & 15;
        size_t m = (size_t)(t0 + st) * BB + b;
        float *dst = (tid < 16) ? (c_s + st) : (tid < 32) ? (d_s + st) : (e_s + st);
        const float *src = (tid < 16) ? (scr_c + m) : (tid < 32) ? (scr_d + m) : (scr_e + m);
        cp_async4(dst, src);
    }
}

__global__ __launch_bounds__(64) void scan_kernel(const float *__restrict__ S0,
                                                  float *__restrict__ out,
                                                  int write_sfinal) {
    __shared__ __align__(16) float sh_kn[2][CH17][64];
    __shared__ __align__(16) float sh_q [2][CH17][64];
    __shared__ __align__(16) float sh_v [2][CHUNK][8];
    __shared__ __align__(16) float sh_g [2][CHUNK][8];
    __shared__ float sh_c[2][CHUNK], sh_d[2][CHUNK], sh_e[2][CHUNK];
    __shared__ float sh_out[CHUNK][8];

    const int b  = blockIdx.x;
    const int r0 = blockIdx.y * 8;
    const int tid = threadIdx.x;
    const int rl = tid >> 3;
    const int cg = tid & 7;
    const int j0 = cg * 8;
    const int row = r0 + rl;

    float s[8], kc[8];
    {
        const float *s0p = S0 + ((size_t)b * 64 + row) * 64 + j0;
#pragma unroll
        for (int j = 0; j < 8; j++) s[j] = s0p[j];
    }
    float rk, rq;
    {
        const float *rp = scr_raw + (size_t)b * NTOT;   // m = 0*B + b
        float qn[8];
#pragma unroll
        for (int j = 0; j < 8; j++) { kc[j] = rp[j0 + j]; qn[j] = rp[128 + j0 + j]; }
        float a = 0.f, c2 = 0.f;
#pragma unroll
        for (int j = 0; j < 8; j++) { a = fmaf(s[j], kc[j], a); c2 = fmaf(s[j], qn[j], c2); }
        a  += __shfl_xor_sync(0xffffffffu, a, 1);
        c2 += __shfl_xor_sync(0xffffffffu, c2, 1);
        a  += __shfl_xor_sync(0xffffffffu, a, 2);
        c2 += __shfl_xor_sync(0xffffffffu, c2, 2);
        a  += __shfl_xor_sync(0xffffffffu, a, 4);
        c2 += __shfl_xor_sync(0xffffffffu, c2, 4);
        rk = a; rq = c2;
    }

    scan_issue(&sh_kn[0][0][0], &sh_q[0][0][0], &sh_v[0][0][0], &sh_g[0][0][0],
               &sh_c[0][0], &sh_d[0][0], &sh_e[0][0], 0, b, r0, tid);
    asm volatile("cp.async.commit_group;");

    for (int ch = 0; ch < NCH; ch++) {
        const int pb = ch & 1;
        if (ch + 1 < NCH) {
            scan_issue(&sh_kn[pb ^ 1][0][0], &sh_q[pb ^ 1][0][0], &sh_v[pb ^ 1][0][0],
                       &sh_g[pb ^ 1][0][0], &sh_c[pb ^ 1][0], &sh_d[pb ^ 1][0],
                       &sh_e[pb ^ 1][0], (ch + 1) * CHUNK, b, r0, tid);
            asm volatile("cp.async.commit_group;");
            asm volatile("cp.async.wait_group 1;");
        } else {
            asm volatile("cp.async.wait_group 0;");
        }
        __syncthreads();

#pragma unroll 2
        for (int st = 0; st < CHUNK; st++) {
            float4 ka0 = *(const float4 *)&sh_kn[pb][st + 1][j0];
            float4 ka1 = *(const float4 *)&sh_kn[pb][st + 1][j0 + 4];
            float4 qa0 = *(const float4 *)&sh_q[pb][st + 1][j0];
            float4 qa1 = *(const float4 *)&sh_q[pb][st + 1][j0 + 4];
            float v  = sh_v[pb][st][rl];
            float g  = sh_g[pb][st][rl];
            float c  = sh_c[pb][st];
            float dd = sh_d[pb][st];
            float ee = sh_e[pb][st];

            float delta = v - rk;                    // scalar fast path
            float Sq = fmaf(g, rq, delta * c);
            if (cg == 0) {
                float sg = 1.0f / (1.0f + __expf(-Sq));
                sh_out[st][rl] = Sq * Sq * sg;       // Sq * silu(Sq)
            }

            // dots on OLD S with NEXT step's kn/q (off critical path)
            float ua = s[0] * ka0.x,  ub = s[1] * ka0.y;
            float wa = s[0] * qa0.x,  wb = s[1] * qa0.y;
            ua = fmaf(s[2], ka0.z, ua); ub = fmaf(s[3], ka0.w, ub);
            wa = fmaf(s[2], qa0.z, wa); wb = fmaf(s[3], qa0.w, wb);
            ua = fmaf(s[4], ka1.x, ua); ub = fmaf(s[5], ka1.y, ub);
            wa = fmaf(s[4], qa1.x, wa); wb = fmaf(s[5], qa1.y, wb);
            ua = fmaf(s[6], ka1.z, ua); ub = fmaf(s[7], ka1.w, ub);
            wa = fmaf(s[6], qa1.z, wa); wb = fmaf(s[7], qa1.w, wb);
            float u = ua + ub, w = wa + wb;

            // state update (kn_t kept in regs)
            s[0] = fmaf(g, s[0], delta * kc[0]);
            s[1] = fmaf(g, s[1], delta * kc[1]);
            s[2] = fmaf(g, s[2], delta * kc[2]);
            s[3] = fmaf(g, s[3], delta * kc[3]);
            s[4] = fmaf(g, s[4], delta * kc[4]);
            s[5] = fmaf(g, s[5], delta * kc[5]);
            s[6] = fmaf(g, s[6], delta * kc[6]);
            s[7] = fmaf(g, s[7], delta * kc[7]);
            kc[0] = ka0.x; kc[1] = ka0.y; kc[2] = ka0.z; kc[3] = ka0.w;
            kc[4] = ka1.x; kc[5] = ka1.y; kc[6] = ka1.z; kc[7] = ka1.w;

            u += __shfl_xor_sync(0xffffffffu, u, 1);
            w += __shfl_xor_sync(0xffffffffu, w, 1);
            u += __shfl_xor_sync(0xffffffffu, u, 2);
            w += __shfl_xor_sync(0xffffffffu, w, 2);
            u += __shfl_xor_sync(0xffffffffu, u, 4);
            w += __shfl_xor_sync(0xffffffffu, w, 4);

            rk = fmaf(g, u, delta * dd);   // rk_{t+1}
            rq = fmaf(g, w, delta * ee);   // rq_{t+1}
        }
        __syncthreads();

        const int t0 = ch * CHUNK;
#pragma unroll
        for (int uq = 0; uq < 2; uq++) {
            int idx = tid + uq * 64;
            int st = idx >> 3, r = idx & 7;
            out[(size_t)(t0 + st) * (BB * NN) + b * NN + r0 + r] = sh_out[st][r];
        }
    }

    if (write_sfinal) {
        float *sf = out + (size_t)TT * BB * NN + ((size_t)b * 64 + row) * 64 + j0;
        *(float4 *)sf       = make_float4(s[0], s[1], s[2], s[3]);
        *(float4 *)(sf + 4) = make_float4(s[4], s[5], s[6], s[7]);
    }
}

// ======================================================================
extern "C" void kernel_launch(void *const *d_in, const int *in_sizes, int n_in,
                              void *d_out, int out_size) {
    const float *x  = (const float *)d_in[0];
    const float *S0 = (const float *)d_in[1];
    const float *Wk = (const float *)d_in[2];
    const float *Wv = (const float *)d_in[3];
    const float *Wq = (const float *)d_in[4];
    const float *Wb = (const float *)d_in[5];
    const float *bb = (const float *)d_in[6];
    float *out = (float *)d_out;

    cudaFuncSetAttribute(mma_gemm_kernel, cudaFuncAttributeMaxDynamicSharedMemorySize,
                         SMEM_GEMM_TOTAL);

    // Weight prep (each kernel is a no-op in the pass that doesn't need it)
    copyw_kernel<<<1024, 256>>>(Wk, Wv, Wq, Wb);
    convw_kernel<<<256, 256>>>(Wk, Wv, Wq, Wb);
    convx_kernel<<<32768, 256>>>(x);

    // GEMM: exactly one of these has a body in the compiled pass
    mma_gemm_kernel<<<MROWS / 128, 128, SMEM_GEMM_TOTAL>>>();
    fb_gemm_kernel<<<dim3(MROWS / 128, 2), 256>>>(x);

    epilogue_kernel<<<4096, 256>>>(bb);
    pair_kernel<<<4096, 256>>>();

    int ws = (out_size >= TT * BB * NN + BB * NN * NN) ? 1 : 0;
    scan_kernel<<<dim3(BB, 8), 64>>>(S0, out, ws);
}

// round 4
// speedup vs baseline: 1.7078x; 1.0042x over previous
#include <cuda_runtime.h>
#include <cuda_bf16.h>
#include <cstdint>
#include <cstddef>

#define TT   2048
#define BB   16
#define DIMK 1024
#define NN   64
#define NTOT 256
#define MROWS (TT*BB)
#define CHUNK 16
#define CH19  (CHUNK+3)
#define NCH   (TT/CHUNK)

// Does this compilation pass support tcgen05 (arch-specific sm_100a/sm_103a)?
#if defined(__CUDA_ARCH__) && (__CUDA_ARCH__ >= 1000) && \
    (defined(__CUDA_ARCH_FEAT_SM103_ALL) || defined(__CUDA_ARCH_FEAT_SM100_ALL))
#define HAS_TC 1
#else
#define HAS_TC 0
#endif

// ---------------- device scratch ----------------
__device__ __align__(128) __nv_bfloat16 g_xhi[(size_t)MROWS * DIMK];
__device__ __align__(128) __nv_bfloat16 g_xlo[(size_t)MROWS * DIMK];
__device__ __align__(128) __nv_bfloat16 g_whi[NTOT * DIMK];
__device__ __align__(128) __nv_bfloat16 g_wlo[NTOT * DIMK];
__device__ __align__(128) float scr_w[NTOT * DIMK];   // packed fp32 weights (fallback path)
// per row m=(t*B+b): [kn(64)|v(64)|q(64)|g(64)]; +4 timesteps of zero pad (never written)
__device__ __align__(128) float scr_raw[(size_t)(MROWS + 4 * BB) * NTOT];
// per row m: [P1,R1,P2,R2,P3,R3,c,0]  (P_j = kn_t.kn_{t+j}, R_j = kn_t.q_{t+j}, c = kn_t.q_t)
__device__ __align__(128) float scr_pr[(size_t)MROWS * 8];

// ---------------- helpers ----------------
#define SWZ(off) ((off) ^ (((off) >> 3) & 0x70))

__device__ __forceinline__ void cp_async16(void *smem_dst, const void *gsrc) {
    unsigned sa = (unsigned)__cvta_generic_to_shared(smem_dst);
    asm volatile("cp.async.ca.shared.global [%0], [%1], 16;" :: "r"(sa), "l"(gsrc));
}

// f32x2 helpers (fallback GEMM)
__device__ __forceinline__ unsigned long long pack2(float x, float y) {
    unsigned long long r;
    asm("mov.b64 %0, {%1, %2};" : "=l"(r) : "f"(x), "f"(y));
    return r;
}
__device__ __forceinline__ void unpack2(unsigned long long v, float &x, float &y) {
    asm("mov.b64 {%0, %1}, %2;" : "=f"(x), "=f"(y) : "l"(v));
}
__device__ __forceinline__ void ffma2(unsigned long long &c, unsigned long long a, unsigned long long b) {
    asm("fma.rn.f32x2 %0, %1, %2, %0;" : "+l"(c) : "l"(a), "l"(b));
}

// split fp32 -> (hi, lo) bf16
__device__ __forceinline__ void split4(float4 v, uint2 &uh, uint2 &ul) {
    __nv_bfloat16 h0 = __float2bfloat16(v.x), h1 = __float2bfloat16(v.y);
    __nv_bfloat16 h2 = __float2bfloat16(v.z), h3 = __float2bfloat16(v.w);
    __nv_bfloat16 l0 = __float2bfloat16(v.x - __bfloat162float(h0));
    __nv_bfloat16 l1 = __float2bfloat16(v.y - __bfloat162float(h1));
    __nv_bfloat16 l2 = __float2bfloat16(v.z - __bfloat162float(h2));
    __nv_bfloat16 l3 = __float2bfloat16(v.w - __bfloat162float(h3));
    uh.x = ((uint32_t)__bfloat16_as_ushort(h1) << 16) | __bfloat16_as_ushort(h0);
    uh.y = ((uint32_t)__bfloat16_as_ushort(h3) << 16) | __bfloat16_as_ushort(h2);
    ul.x = ((uint32_t)__bfloat16_as_ushort(l1) << 16) | __bfloat16_as_ushort(l0);
    ul.y = ((uint32_t)__bfloat16_as_ushort(l3) << 16) | __bfloat16_as_ushort(l2);
}

#if HAS_TC
__device__ __forceinline__ uint64_t make_desc(uint32_t a) {
    return ((uint64_t)2 << 61) | ((uint64_t)1 << 46) | ((uint64_t)64 << 32) |
           ((uint64_t)1 << 16) | ((a >> 4) & 0x3FFF);
}
__device__ __forceinline__ void mbar_init(uint32_t addr, uint32_t cnt) {
    asm volatile("mbarrier.init.shared.b64 [%0], %1;" :: "r"(addr), "r"(cnt) : "memory");
}
__device__ __forceinline__ void mbar_wait(uint32_t addr, uint32_t parity) {
    uint32_t done;
    asm volatile(
        "{\n\t.reg .pred p;\n\t"
        "mbarrier.try_wait.parity.acquire.cta.shared::cta.b64 p, [%1], %2;\n\t"
        "selp.b32 %0, 1, 0, p;\n\t}"
        : "=r"(done) : "r"(addr), "r"(parity) : "memory");
    if (!done) {
        asm volatile(
            "{\n\t.reg .pred P1;\n\t"
            "WL_%=:\n\t"
            "mbarrier.try_wait.parity.acquire.cta.shared::cta.b64 P1, [%0], %1, 0x989680;\n\t"
            "@P1 bra.uni WD_%=;\n\t"
            "bra.uni WL_%=;\n\t"
            "WD_%=:\n\t}"
            :: "r"(addr), "r"(parity) : "memory");
    }
}
__device__ __forceinline__ void mma_f16_ss(uint32_t d, uint64_t a, uint64_t b,
                                           uint32_t idesc, uint32_t en) {
    asm volatile(
        "{\n\t.reg .pred p;\n\t"
        "setp.ne.u32 p, %5, 0;\n\t"
        "tcgen05.mma.cta_group::1.kind::f16 [%0], %1, %2, %3, {%4, %4, %4, %4}, p;\n\t}"
        :: "r"(d), "l"(a), "l"(b), "r"(idesc), "r"(0u), "r"(en) : "memory");
}
#endif

// ======================================================================
// Weight / activation prep kernels (each a no-op in the pass that
// doesn't need it)
// ======================================================================
__global__ void copyw_kernel(const float *__restrict__ wk, const float *__restrict__ wv,
                             const float *__restrict__ wq, const float *__restrict__ wb) {
#if !HAS_TC
    int i = blockIdx.x * 256 + threadIdx.x;
    int sel = i >> 16, off = i & 65535;
    const float *src = (sel == 0) ? wk : (sel == 1) ? wv : (sel == 2) ? wq : wb;
    scr_w[i] = src[off];
#endif
}

__global__ void convw_kernel(const float *__restrict__ wk, const float *__restrict__ wv,
                             const float *__restrict__ wq, const float *__restrict__ wb) {
#if HAS_TC
    int g = blockIdx.x * 256 + threadIdx.x;
    int i4 = g * 4;
    int n = i4 >> 10, k = i4 & 1023;
    int sel = n >> 6, r = n & 63;
    const float *src = (sel == 0) ? wk : (sel == 1) ? wv : (sel == 2) ? wq : wb;
    float4 v = *(const float4 *)(src + (size_t)r * DIMK + k);
    uint2 uh, ul;
    split4(v, uh, ul);
    *(uint2 *)(g_whi + i4) = uh;
    *(uint2 *)(g_wlo + i4) = ul;
#endif
}

__global__ void convx_kernel(const float *__restrict__ x) {
#if HAS_TC
    size_t i4 = ((size_t)blockIdx.x * 256 + threadIdx.x) * 4;
    float4 v = *(const float4 *)(x + i4);
    uint2 uh, ul;
    split4(v, uh, ul);
    *(uint2 *)(g_xhi + i4) = uh;
    *(uint2 *)(g_xlo + i4) = ul;
#endif
}

// ======================================================================
// Fallback fp32 GEMM (body only in non-tcgen05 passes)
// ======================================================================
__global__ __launch_bounds__(256, 2) void fb_gemm_kernel(const float *__restrict__ X) {
#if !HAS_TC
    __shared__ __align__(16) float As[16 * 128];
    __shared__ __align__(16) float Bs[16 * 128];

    const int tid = threadIdx.x;
    const int m0 = blockIdx.x * 128;
    const int n0 = blockIdx.y * 128;
    const int tm = tid >> 4;
    const int tn = tid & 15;

    unsigned long long acc[4][8];
#pragma unroll
    for (int i = 0; i < 4; i++)
#pragma unroll
        for (int j = 0; j < 8; j++) acc[i][j] = 0ull;

    const int u0 = tid * 2;
    const int arow0 = u0 >> 2,       ac40 = u0 & 3;
    const int arow1 = (u0 + 1) >> 2, ac41 = (u0 + 1) & 3;

    const float *Xb = X + (size_t)m0 * DIMK;
    const float *Wb = scr_w + (size_t)n0 * DIMK;

    for (int kt = 0; kt < DIMK; kt += 16) {
        float4 a0 = *(const float4 *)(Xb + (size_t)arow0 * DIMK + kt + ac40 * 4);
        float4 a1 = *(const float4 *)(Xb + (size_t)arow1 * DIMK + kt + ac41 * 4);
        float4 b0 = *(const float4 *)(Wb + (size_t)arow0 * DIMK + kt + ac40 * 4);
        float4 b1 = *(const float4 *)(Wb + (size_t)arow1 * DIMK + kt + ac41 * 4);

        __syncthreads();
        {
            int k0 = ac40 * 4, k1 = ac41 * 4;
            As[(k0 + 0) * 128 + arow0] = a0.x; As[(k0 + 1) * 128 + arow0] = a0.y;
            As[(k0 + 2) * 128 + arow0] = a0.z; As[(k0 + 3) * 128 + arow0] = a0.w;
            As[(k1 + 0) * 128 + arow1] = a1.x; As[(k1 + 1) * 128 + arow1] = a1.y;
            As[(k1 + 2) * 128 + arow1] = a1.z; As[(k1 + 3) * 128 + arow1] = a1.w;
            Bs[(k0 + 0) * 128 + arow0] = b0.x; Bs[(k0 + 1) * 128 + arow0] = b0.y;
            Bs[(k0 + 2) * 128 + arow0] = b0.z; Bs[(k0 + 3) * 128 + arow0] = b0.w;
            Bs[(k1 + 0) * 128 + arow1] = b1.x; Bs[(k1 + 1) * 128 + arow1] = b1.y;
            Bs[(k1 + 2) * 128 + arow1] = b1.z; Bs[(k1 + 3) * 128 + arow1] = b1.w;
        }
        __syncthreads();

#pragma unroll
        for (int k = 0; k < 16; k++) {
            const ulonglong2 *pa = (const ulonglong2 *)&As[k * 128 + tm * 8];
            ulonglong2 av0 = pa[0];
            ulonglong2 av1 = pa[1];
            float4 bv0 = *(const float4 *)&Bs[k * 128 + tn * 8];
            float4 bv1 = *(const float4 *)&Bs[k * 128 + tn * 8 + 4];
            unsigned long long ap[4] = {av0.x, av0.y, av1.x, av1.y};
            unsigned long long bbx[8];
            bbx[0] = pack2(bv0.x, bv0.x); bbx[1] = pack2(bv0.y, bv0.y);
            bbx[2] = pack2(bv0.z, bv0.z); bbx[3] = pack2(bv0.w, bv0.w);
            bbx[4] = pack2(bv1.x, bv1.x); bbx[5] = pack2(bv1.y, bv1.y);
            bbx[6] = pack2(bv1.z, bv1.z); bbx[7] = pack2(bv1.w, bv1.w);
#pragma unroll
            for (int mp = 0; mp < 4; mp++)
#pragma unroll
                for (int n = 0; n < 8; n++)
                    ffma2(acc[mp][n], ap[mp], bbx[n]);
        }
    }

#pragma unroll
    for (int mp = 0; mp < 4; mp++) {
        float lo[8], hi[8];
#pragma unroll
        for (int n = 0; n < 8; n++) unpack2(acc[mp][n], lo[n], hi[n]);
        int mA = m0 + tm * 8 + mp * 2;
        float *outp = scr_raw + (size_t)mA * NTOT + n0 + tn * 8;
        *(float4 *)(outp)            = make_float4(lo[0], lo[1], lo[2], lo[3]);
        *(float4 *)(outp + 4)        = make_float4(lo[4], lo[5], lo[6], lo[7]);
        *(float4 *)(outp + NTOT)     = make_float4(hi[0], hi[1], hi[2], hi[3]);
        *(float4 *)(outp + NTOT + 4) = make_float4(hi[4], hi[5], hi[6], hi[7]);
    }
#endif
}

// ======================================================================
// tcgen05 GEMM (body only in arch-specific passes) — unchanged from R3
// ======================================================================
#define GK 64
#define NKC (DIMK / GK)
#define A_BYTES  (128 * 128)
#define B_BYTES  (256 * 128)
#define ST_BYTES (2 * A_BYTES + 2 * B_BYTES)          // 96 KB
#define SMEM_GEMM_TOTAL (1024 + 2 * ST_BYTES)
#define G_IDESC ((1u << 4) | (1u << 7) | (1u << 10) | ((NTOT / 8) << 17) | ((128 / 16) << 24))

extern __shared__ __align__(1024) char gsm[];

#if HAS_TC
__device__ __forceinline__ void g_load_chunk(char *stp, int m0, int kc, int tid) {
    const char *xh = (const char *)(g_xhi + (size_t)m0 * DIMK + kc * GK);
    const char *xl = (const char *)(g_xlo + (size_t)m0 * DIMK + kc * GK);
#pragma unroll
    for (int i = 0; i < 8; i++) {
        int idx = tid + i * 128;
        int row = idx >> 3, gr = idx & 7;
        uint32_t sw = SWZ(row * 128 + gr * 16);
        size_t gof = (size_t)row * (DIMK * 2) + gr * 16;
        cp_async16(stp + sw, xh + gof);
        cp_async16(stp + A_BYTES + sw, xl + gof);
    }
    const char *wh = (const char *)(g_whi + kc * GK);
    const char *wl = (const char *)(g_wlo + kc * GK);
#pragma unroll
    for (int i = 0; i < 16; i++) {
        int idx = tid + i * 128;
        int row = idx >> 3, gr = idx & 7;
        uint32_t sw = SWZ(row * 128 + gr * 16);
        size_t gof = (size_t)row * (DIMK * 2) + gr * 16;
        cp_async16(stp + 2 * A_BYTES + sw, wh + gof);
        cp_async16(stp + 2 * A_BYTES + B_BYTES + sw, wl + gof);
    }
}
#endif

__global__ __launch_bounds__(128, 1)
void mma_gemm_kernel() {
#if HAS_TC
    const int tid = threadIdx.x, wid = tid >> 5, lid = tid & 31;
    const int m0 = blockIdx.x * 128;
    uint32_t sbase = (uint32_t)__cvta_generic_to_shared(gsm);

    if (wid == 0) {
        asm volatile("tcgen05.alloc.cta_group::1.sync.aligned.shared::cta.b32 [%0], %1;"
                     :: "r"(sbase), "r"(256u) : "memory");
        asm volatile("tcgen05.relinquish_alloc_permit.cta_group::1.sync.aligned;");
    }
    if (tid == 0) { mbar_init(sbase + 16, 1); mbar_init(sbase + 24, 1); }
    __syncthreads();
    uint32_t tmem;
    asm volatile("ld.shared.b32 %0, [%1];" : "=r"(tmem) : "r"(sbase));

    g_load_chunk(gsm + 1024, m0, 0, tid);
    asm volatile("cp.async.commit_group;");
    g_load_chunk(gsm + 1024 + ST_BYTES, m0, 1, tid);
    asm volatile("cp.async.commit_group;");

    int ph0 = 0, ph1 = 0;
    for (int c = 0; c < NKC; c++) {
        int s = c & 1;
        char *stp = gsm + 1024 + s * ST_BYTES;
        uint32_t sa = sbase + 1024 + s * ST_BYTES;
        if (c < NKC - 1) asm volatile("cp.async.wait_group 1;" ::: "memory");
        else             asm volatile("cp.async.wait_group 0;" ::: "memory");
        __syncthreads();

        if (tid == 0) {
            asm volatile("fence.proxy.async.shared::cta;" ::: "memory");
            uint64_t ahi = make_desc(sa);
            uint64_t alo = make_desc(sa + A_BYTES);
            uint64_t bhi = make_desc(sa + 2 * A_BYTES);
            uint64_t blo = make_desc(sa + 2 * A_BYTES + B_BYTES);
#pragma unroll
            for (int k = 0; k < 4; k++)
                mma_f16_ss(tmem, ahi + k * 2, bhi + k * 2, G_IDESC, !(c == 0 && k == 0));
#pragma unroll
            for (int k = 0; k < 4; k++)
                mma_f16_ss(tmem, ahi + k * 2, blo + k * 2, G_IDESC, 1u);
#pragma unroll
            for (int k = 0; k < 4; k++)
                mma_f16_ss(tmem, alo + k * 2, bhi + k * 2, G_IDESC, 1u);
            asm volatile(
                "tcgen05.commit.cta_group::1.mbarrier::arrive::one.shared::cluster.b64 [%0];"
                :: "r"(sbase + 16 + s * 8) : "memory");
        }
        if (c + 2 < NKC) {
            if (s == 0) { mbar_wait(sbase + 16, ph0 & 1); ph0++; }
            else        { mbar_wait(sbase + 24, ph1 & 1); ph1++; }
            g_load_chunk(stp, m0, c + 2, tid);
            asm volatile("cp.async.commit_group;");
        }
    }
    mbar_wait(sbase + 16, ph0 & 1);
    mbar_wait(sbase + 24, ph1 & 1);
    asm volatile("tcgen05.fence::after_thread_sync;" ::: "memory");

    float *orow = scr_raw + (size_t)(m0 + wid * 32 + lid) * NTOT;
#pragma unroll 1
    for (int cb = 0; cb < 8; cb++) {
        uint32_t r[32];
        asm volatile(
            "tcgen05.ld.sync.aligned.32x32b.x32.b32 "
            "{%0, %1, %2, %3, %4, %5, %6, %7, "
            " %8, %9, %10, %11, %12, %13, %14, %15, "
            " %16, %17, %18, %19, %20, %21, %22, %23, "
            " %24, %25, %26, %27, %28, %29, %30, %31}, [%32];"
            : "=r"(r[0]), "=r"(r[1]), "=r"(r[2]), "=r"(r[3]), "=r"(r[4]), "=r"(r[5]),
              "=r"(r[6]), "=r"(r[7]), "=r"(r[8]), "=r"(r[9]), "=r"(r[10]), "=r"(r[11]),
              "=r"(r[12]), "=r"(r[13]), "=r"(r[14]), "=r"(r[15]), "=r"(r[16]), "=r"(r[17]),
              "=r"(r[18]), "=r"(r[19]), "=r"(r[20]), "=r"(r[21]), "=r"(r[22]), "=r"(r[23]),
              "=r"(r[24]), "=r"(r[25]), "=r"(r[26]), "=r"(r[27]), "=r"(r[28]), "=r"(r[29]),
              "=r"(r[30]), "=r"(r[31])
            : "r"(tmem + cb * 32));
        asm volatile("tcgen05.wait::ld.sync.aligned;" ::: "memory");
        float4 *o4 = (float4 *)(orow + cb * 32);
#pragma unroll
        for (int i = 0; i < 8; i++)
            o4[i] = make_float4(__uint_as_float(r[i * 4]), __uint_as_float(r[i * 4 + 1]),
                                __uint_as_float(r[i * 4 + 2]), __uint_as_float(r[i * 4 + 3]));
    }
    __syncthreads();
    if (wid == 0)
        asm volatile("tcgen05.dealloc.cta_group::1.sync.aligned.b32 %0, %1;"
                     :: "r"(tmem), "r"(256u));
#endif
}

// ======================================================================
// Epilogue: kn = k/(|k|+eps), g = sigmoid(beta+b)   (1 warp/row)
// ======================================================================
__global__ void epilogue_kernel(const float *__restrict__ b_beta) {
    int warp = (blockIdx.x * blockDim.x + threadIdx.x) >> 5;
    int lane = threadIdx.x & 31;
    if (warp >= MROWS) return;
    float *row = scr_raw + (size_t)warp * NTOT;
    int i0 = lane * 2;

    float2 kv = *(float2 *)(row + i0);
    float2 bt = *(float2 *)(row + 192 + i0);

    float nk = kv.x * kv.x + kv.y * kv.y;
#pragma unroll
    for (int off = 16; off; off >>= 1) nk += __shfl_xor_sync(0xffffffffu, nk, off);
    float inv = 1.0f / (sqrtf(nk) + 1e-6f);

    float gx = 1.0f / (1.0f + __expf(-(bt.x + b_beta[i0])));
    float gy = 1.0f / (1.0f + __expf(-(bt.y + b_beta[i0 + 1])));

    *(float2 *)(row + i0)       = make_float2(kv.x * inv, kv.y * inv);
    *(float2 *)(row + 192 + i0) = make_float2(gx, gy);
}

// ======================================================================
// Pair kernel: per row m, scr_pr[m] = {P1,R1,P2,R2,P3,R3,c,0}
//   P_j = kn_m . kn_{m+jB},  R_j = kn_m . q_{m+jB},  c = kn_m . q_m
// Pad rows (t >= T) are zero -> dots 0 at the boundary.
// ======================================================================
__global__ void pair_kernel() {
    int warp = (blockIdx.x * blockDim.x + threadIdx.x) >> 5;
    int lane = threadIdx.x & 31;
    if (warp >= MROWS) return;
    const float *r0 = scr_raw + (size_t)warp * NTOT;
    const float *r1 = scr_raw + (size_t)(warp + BB) * NTOT;
    const float *r2 = scr_raw + (size_t)(warp + 2 * BB) * NTOT;
    const float *r3 = scr_raw + (size_t)(warp + 3 * BB) * NTOT;
    int i0 = lane * 2;

    float2 k0 = *(const float2 *)(r0 + i0);
    float2 q0 = *(const float2 *)(r0 + 128 + i0);
    float2 k1 = *(const float2 *)(r1 + i0);
    float2 q1 = *(const float2 *)(r1 + 128 + i0);
    float2 k2 = *(const float2 *)(r2 + i0);
    float2 q2 = *(const float2 *)(r2 + 128 + i0);
    float2 k3 = *(const float2 *)(r3 + i0);
    float2 q3 = *(const float2 *)(r3 + 128 + i0);

    float c  = k0.x * q0.x + k0.y * q0.y;
    float P1 = k0.x * k1.x + k0.y * k1.y;
    float R1 = k0.x * q1.x + k0.y * q1.y;
    float P2 = k0.x * k2.x + k0.y * k2.y;
    float R2 = k0.x * q2.x + k0.y * q2.y;
    float P3 = k0.x * k3.x + k0.y * k3.y;
    float R3 = k0.x * q3.x + k0.y * q3.y;
#pragma unroll
    for (int off = 16; off; off >>= 1) {
        c  += __shfl_xor_sync(0xffffffffu, c,  off);
        P1 += __shfl_xor_sync(0xffffffffu, P1, off);
        R1 += __shfl_xor_sync(0xffffffffu, R1, off);
        P2 += __shfl_xor_sync(0xffffffffu, P2, off);
        R2 += __shfl_xor_sync(0xffffffffu, R2, off);
        P3 += __shfl_xor_sync(0xffffffffu, P3, off);
        R3 += __shfl_xor_sync(0xffffffffu, R3, off);
    }
    if (lane == 0) {
        float *pr = scr_pr + (size_t)warp * 8;
        *(float4 *)pr       = make_float4(P1, R1, P2, R2);
        *(float4 *)(pr + 4) = make_float4(P3, R3, c, 0.0f);
    }
}

// ======================================================================
// Scan with depth-4 software-pipelined lookahead.
// grid (B=16, 8 row-groups), 64 threads (8 rows x 8 lanes).
// Per step t the serial chain is only: delta_t -> FMA -> rk_{t+1}.
// ======================================================================
__device__ __forceinline__ void scan_issue(float *kn_s, float *q_s, float *v_s, float *g_s,
                                           float *pr_s, int t0, int b, int r0, int tid) {
    // kn, q: CH19 steps * 16 float4 = 304 units each
#pragma unroll
    for (int i = 0; i < 5; i++) {
        int u = tid + i * 64;
        if (u < CH19 * 16) {
            int st = u >> 4, f4 = u & 15;
            size_t m = (size_t)(t0 + st) * BB + b;
            cp_async16(kn_s + st * 64 + f4 * 4, scr_raw + m * NTOT + f4 * 4);
            cp_async16(q_s  + st * 64 + f4 * 4, scr_raw + m * NTOT + 128 + f4 * 4);
        }
    }
    {
        int st = (tid & 31) >> 1, part = tid & 1;
        size_t m = (size_t)(t0 + st) * BB + b;
        if (tid < 32) cp_async16(v_s + st * 8 + part * 4, scr_raw + m * NTOT + 64 + r0 + part * 4);
        else          cp_async16(g_s + st * 8 + part * 4, scr_raw + m * NTOT + 192 + r0 + part * 4);
    }
    if (tid < 32) {
        int st = tid >> 1, half = tid & 1;
        size_t m = (size_t)(t0 + st) * BB + b;
        cp_async16(pr_s + st * 8 + half * 4, scr_pr + m * 8 + half * 4);
    }
}

// full dot of s[8] with 8 consecutive floats at p, reduced over the 8-lane group
__device__ __forceinline__ float dot_full(const float *s, const float *p) {
    float4 a = *(const float4 *)p, b = *(const float4 *)(p + 4);
    float x = s[0] * a.x, y = s[1] * a.y;
    x = fmaf(s[2], a.z, x); y = fmaf(s[3], a.w, y);
    x = fmaf(s[4], b.x, x); y = fmaf(s[5], b.y, y);
    x = fmaf(s[6], b.z, x); y = fmaf(s[7], b.w, y);
    float r = x + y;
    r += __shfl_xor_sync(0xffffffffu, r, 1);
    r += __shfl_xor_sync(0xffffffffu, r, 2);
    r += __shfl_xor_sync(0xffffffffu, r, 4);
    return r;
}
// partial dot with only 2 reduction levels applied
__device__ __forceinline__ float dot_2lvl(const float *s, const float *p) {
    float4 a = *(const float4 *)p, b = *(const float4 *)(p + 4);
    float x = s[0] * a.x, y = s[1] * a.y;
    x = fmaf(s[2], a.z, x); y = fmaf(s[3], a.w, y);
    x = fmaf(s[4], b.x, x); y = fmaf(s[5], b.y, y);
    x = fmaf(s[6], b.z, x); y = fmaf(s[7], b.w, y);
    float r = x + y;
    r += __shfl_xor_sync(0xffffffffu, r, 1);
    r += __shfl_xor_sync(0xffffffffu, r, 2);
    return r;
}

__global__ __launch_bounds__(64) void scan_kernel(const float *__restrict__ S0,
                                                  float *__restrict__ out,
                                                  int write_sfinal) {
    __shared__ __align__(16) float sh_kn[2][CH19][64];
    __shared__ __align__(16) float sh_q [2][CH19][64];
    __shared__ __align__(16) float sh_v [2][CHUNK][8];
    __shared__ __align__(16) float sh_g [2][CHUNK][8];
    __shared__ __align__(16) float sh_pr[2][CHUNK][8];
    __shared__ float sh_out[CHUNK][8];

    const int b  = blockIdx.x;
    const int r0 = blockIdx.y * 8;
    const int tid = threadIdx.x;
    const int rl = tid >> 3;         // row-local 0..7
    const int cg = tid & 7;          // lane within row
    const int j0 = cg * 8;
    const int row = r0 + rl;
    const float mask = (cg == 0) ? 1.0f : 0.0f;

    float s[8];
    {
        const float *s0p = S0 + ((size_t)b * 64 + row) * 64 + j0;
#pragma unroll
        for (int j = 0; j < 8; j++) s[j] = s0p[j];
    }

    // ---- prologue: seed rk/rq (target 0), A (target 1, full), B (target 2, 2 lvls) ----
    float rk, rq, Ak, Aq, Bk, Bq;
    {
        const float *p0 = scr_raw + ((size_t)0 * BB + b) * NTOT;
        const float *p1 = scr_raw + ((size_t)1 * BB + b) * NTOT;
        const float *p2 = scr_raw + ((size_t)2 * BB + b) * NTOT;
        rk = dot_full(s, p0 + j0);       rq = dot_full(s, p0 + 128 + j0);
        Ak = dot_full(s, p1 + j0);       Aq = dot_full(s, p1 + 128 + j0);
        Bk = dot_2lvl(s, p2 + j0);       Bq = dot_2lvl(s, p2 + 128 + j0);
    }

    scan_issue(&sh_kn[0][0][0], &sh_q[0][0][0], &sh_v[0][0][0], &sh_g[0][0][0],
               &sh_pr[0][0][0], 0, b, r0, tid);
    asm volatile("cp.async.commit_group;");

    for (int ch = 0; ch < NCH; ch++) {
        const int pb = ch & 1;
        if (ch + 1 < NCH) {
            scan_issue(&sh_kn[pb ^ 1][0][0], &sh_q[pb ^ 1][0][0], &sh_v[pb ^ 1][0][0],
                       &sh_g[pb ^ 1][0][0], &sh_pr[pb ^ 1][0][0],
                       (ch + 1) * CHUNK, b, r0, tid);
            asm volatile("cp.async.commit_group;");
            asm volatile("cp.async.wait_group 1;");
        } else {
            asm volatile("cp.async.wait_group 0;");
        }
        __syncthreads();

#pragma unroll
        for (int st = 0; st < CHUNK; st++) {
            // B final reduction level — top of step, independent of this step's delta
            Bk += __shfl_xor_sync(0xffffffffu, Bk, 4);
            Bq += __shfl_xor_sync(0xffffffffu, Bq, 4);

            const float v = sh_v[pb][st][rl];
            const float g = sh_g[pb][st][rl];
            const float4 pr0 = *(const float4 *)&sh_pr[pb][st][0];  // P1,R1,P2,R2
            const float4 pr1 = *(const float4 *)&sh_pr[pb][st][4];  // P3,R3,c,0

            // ---- serial fast path ----
            const float delta = v - rk;
            const float Sq = fmaf(g, rq, delta * pr1.z);
            if (cg == 0) {
                float sg = 1.0f / (1.0f + __expf(-Sq));
                sh_out[st][rl] = Sq * Sq * sg;       // Sq * silu(Sq)
            }

            // A -> rk for next step (2 FMAs after delta: the whole serial chain)
            const float rk_n = fmaf(g, Ak, delta * pr0.x);
            const float rq_n = fmaf(g, Aq, delta * pr0.y);

            // B uniform correction (after its final level above)
            const float Bk_n = fmaf(g, Bk, delta * pr0.z);
            const float Bq_n = fmaf(g, Bq, delta * pr0.w);

            // ---- create C: dot of OLD state with kn_{t+3}, q_{t+3} ----
            const float4 k3a = *(const float4 *)&sh_kn[pb][st + 3][j0];
            const float4 k3b = *(const float4 *)&sh_kn[pb][st + 3][j0 + 4];
            const float4 q3a = *(const float4 *)&sh_q[pb][st + 3][j0];
            const float4 q3b = *(const float4 *)&sh_q[pb][st + 3][j0 + 4];
            float cx = s[0] * k3a.x, cy = s[1] * k3a.y;
            float dx = s[0] * q3a.x, dy = s[1] * q3a.y;
            cx = fmaf(s[2], k3a.z, cx); cy = fmaf(s[3], k3a.w, cy);
            dx = fmaf(s[2], q3a.z, dx); dy = fmaf(s[3], q3a.w, dy);
            cx = fmaf(s[4], k3b.x, cx); cy = fmaf(s[5], k3b.y, cy);
            dx = fmaf(s[4], q3b.x, dx); dy = fmaf(s[5], q3b.y, dy);
            cx = fmaf(s[6], k3b.z, cx); cy = fmaf(s[7], k3b.w, cy);
            dx = fmaf(s[6], q3b.z, dx); dy = fmaf(s[7], q3b.w, dy);
            float Ck = cx + cy;
            float Cq = dx + dy;

            // masked single-lane correction on the per-lane partials (pre-reduction)
            const float md = mask * delta;
            Ck = fmaf(g, Ck, md * pr1.x);
            Cq = fmaf(g, Cq, md * pr1.y);
            // C reduction levels 1,2
            Ck += __shfl_xor_sync(0xffffffffu, Ck, 1);
            Cq += __shfl_xor_sync(0xffffffffu, Cq, 1);
            Ck += __shfl_xor_sync(0xffffffffu, Ck, 2);
            Cq += __shfl_xor_sync(0xffffffffu, Cq, 2);

            // ---- state update with kn_t ----
            const float4 k0a = *(const float4 *)&sh_kn[pb][st][j0];
            const float4 k0b = *(const float4 *)&sh_kn[pb][st][j0 + 4];
            s[0] = fmaf(g, s[0], delta * k0a.x);
            s[1] = fmaf(g, s[1], delta * k0a.y);
            s[2] = fmaf(g, s[2], delta * k0a.z);
            s[3] = fmaf(g, s[3], delta * k0a.w);
            s[4] = fmaf(g, s[4], delta * k0b.x);
            s[5] = fmaf(g, s[5], delta * k0b.y);
            s[6] = fmaf(g, s[6], delta * k0b.z);
            s[7] = fmaf(g, s[7], delta * k0b.w);

            // rotate pipeline
            rk = rk_n; rq = rq_n;
            Ak = Bk_n; Aq = Bq_n;
            Bk = Ck;   Bq = Cq;
        }
        __syncthreads();

        const int t0 = ch * CHUNK;
#pragma unroll
        for (int uq = 0; uq < 2; uq++) {
            int idx = tid + uq * 64;
            int st2 = idx >> 3, r = idx & 7;
            out[(size_t)(t0 + st2) * (BB * NN) + b * NN + r0 + r] = sh_out[st2][r];
        }
    }

    if (write_sfinal) {
        float *sf = out + (size_t)TT * BB * NN + ((size_t)b * 64 + row) * 64 + j0;
        *(float4 *)sf       = make_float4(s[0], s[1], s[2], s[3]);
        *(float4 *)(sf + 4) = make_float4(s[4], s[5], s[6], s[7]);
    }
}

// ======================================================================
extern "C" void kernel_launch(void *const *d_in, const int *in_sizes, int n_in,
                              void *d_out, int out_size) {
    const float *x  = (const float *)d_in[0];
    const float *S0 = (const float *)d_in[1];
    const float *Wk = (const float *)d_in[2];
    const float *Wv = (const float *)d_in[3];
    const float *Wq = (const float *)d_in[4];
    const float *Wb = (const float *)d_in[5];
    const float *bb = (const float *)d_in[6];
    float *out = (float *)d_out;

    cudaFuncSetAttribute(mma_gemm_kernel, cudaFuncAttributeMaxDynamicSharedMemorySize,
                         SMEM_GEMM_TOTAL);

    copyw_kernel<<<1024, 256>>>(Wk, Wv, Wq, Wb);
    convw_kernel<<<256, 256>>>(Wk, Wv, Wq, Wb);
    convx_kernel<<<32768, 256>>>(x);

    mma_gemm_kernel<<<MROWS / 128, 128, SMEM_GEMM_TOTAL>>>();
    fb_gemm_kernel<<<dim3(MROWS / 128, 2), 256>>>(x);

    epilogue_kernel<<<4096, 256>>>(bb);
    pair_kernel<<<4096, 256>>>();

    int ws = (out_size >= TT * BB * NN + BB * NN * NN) ? 1 : 0;
    scan_kernel<<<dim3(BB, 8), 64>>>(S0, out, ws);
}